// round 1
// baseline (speedup 1.0000x reference)
#include <cuda_runtime.h>

#define DD 128
#define NODES_PER_TILE 64

// ---------------------------------------------------------------------------
// Dense kernel: out[n,:] = h[n,:] @ loop_w + exp(-time_diff[n]*0.1) * (prev[n,:] @ time_w)
// Register-tiled, weights staged in smem in k-chunks of 16.
// Block: 256 threads, tile = 64 nodes x 128 cols.
// Thread (colg = tid&15, nrow = tid>>4): 8 cols x 4 nodes x 2 matrices.
// ---------------------------------------------------------------------------
__global__ __launch_bounds__(256, 2)
void dense_kernel(const float* __restrict__ h,
                  const float* __restrict__ prev,
                  const float* __restrict__ time_diff,
                  const float* __restrict__ loop_w,
                  const float* __restrict__ time_w,
                  float* __restrict__ out, int N)
{
    __shared__ float w1s[16][DD];   // loop_w k-chunk
    __shared__ float w2s[16][DD];   // time_w k-chunk
    __shared__ float hs[16][NODES_PER_TILE];   // transposed h tile
    __shared__ float ps[16][NODES_PER_TILE];   // transposed prev tile

    const int tid  = threadIdx.x;
    const int colg = tid & 15;     // 16 col groups of 8
    const int nrow = tid >> 4;     // 16 node rows (x4 via stride 16)
    const int tile = blockIdx.x * NODES_PER_TILE;

    float4 a1[4][2];
    float4 a2[4][2];
#pragma unroll
    for (int s = 0; s < 4; s++)
#pragma unroll
        for (int j = 0; j < 2; j++) {
            a1[s][j] = make_float4(0.f, 0.f, 0.f, 0.f);
            a2[s][j] = make_float4(0.f, 0.f, 0.f, 0.f);
        }

    const int stage_n  = tid >> 2;   // 0..63
    const int stage_c4 = tid & 3;    // 0..3 (float4 within 16-k chunk)
    const int stage_node = tile + stage_n;
    const bool stage_ok = (stage_node < N);

#pragma unroll 1
    for (int kc = 0; kc < 8; kc++) {
        const int k0 = kc * 16;
        __syncthreads();
        // stage weights: 512 float4 per matrix, 256 threads x 2
#pragma unroll
        for (int r = 0; r < 2; r++) {
            int idx = tid + r * 256;     // 0..511
            int kk  = idx >> 5;          // 0..15
            int c4  = idx & 31;          // 0..31
            float4 v1 = ((const float4*)(loop_w + (size_t)(k0 + kk) * DD))[c4];
            float4 v2 = ((const float4*)(time_w + (size_t)(k0 + kk) * DD))[c4];
            ((float4*)&w1s[kk][0])[c4] = v1;
            ((float4*)&w2s[kk][0])[c4] = v2;
        }
        // stage h/prev tile, transposed
        {
            float4 vh = make_float4(0.f, 0.f, 0.f, 0.f);
            float4 vp = make_float4(0.f, 0.f, 0.f, 0.f);
            if (stage_ok) {
                vh = ((const float4*)(h    + (size_t)stage_node * DD + k0))[stage_c4];
                vp = ((const float4*)(prev + (size_t)stage_node * DD + k0))[stage_c4];
            }
            int kk = stage_c4 * 4;
            hs[kk + 0][stage_n] = vh.x; hs[kk + 1][stage_n] = vh.y;
            hs[kk + 2][stage_n] = vh.z; hs[kk + 3][stage_n] = vh.w;
            ps[kk + 0][stage_n] = vp.x; ps[kk + 1][stage_n] = vp.y;
            ps[kk + 2][stage_n] = vp.z; ps[kk + 3][stage_n] = vp.w;
        }
        __syncthreads();

#pragma unroll
        for (int kk = 0; kk < 16; kk++) {
            float4 wa = ((const float4*)&w1s[kk][0])[colg * 2 + 0];
            float4 wb = ((const float4*)&w1s[kk][0])[colg * 2 + 1];
            float4 ua = ((const float4*)&w2s[kk][0])[colg * 2 + 0];
            float4 ub = ((const float4*)&w2s[kk][0])[colg * 2 + 1];
#pragma unroll
            for (int s = 0; s < 4; s++) {
                float hv = hs[kk][nrow + s * 16];
                float pv = ps[kk][nrow + s * 16];
                a1[s][0].x += hv * wa.x; a1[s][0].y += hv * wa.y;
                a1[s][0].z += hv * wa.z; a1[s][0].w += hv * wa.w;
                a1[s][1].x += hv * wb.x; a1[s][1].y += hv * wb.y;
                a1[s][1].z += hv * wb.z; a1[s][1].w += hv * wb.w;
                a2[s][0].x += pv * ua.x; a2[s][0].y += pv * ua.y;
                a2[s][0].z += pv * ua.z; a2[s][0].w += pv * ua.w;
                a2[s][1].x += pv * ub.x; a2[s][1].y += pv * ub.y;
                a2[s][1].z += pv * ub.z; a2[s][1].w += pv * ub.w;
            }
        }
    }

    // epilogue
#pragma unroll
    for (int s = 0; s < 4; s++) {
        int node = tile + nrow + s * 16;
        if (node >= N) continue;
        float dec = __expf(-__ldg(time_diff + node) * 0.1f);
        float4 o0, o1;
        o0.x = a1[s][0].x + dec * a2[s][0].x;
        o0.y = a1[s][0].y + dec * a2[s][0].y;
        o0.z = a1[s][0].z + dec * a2[s][0].z;
        o0.w = a1[s][0].w + dec * a2[s][0].w;
        o1.x = a1[s][1].x + dec * a2[s][1].x;
        o1.y = a1[s][1].y + dec * a2[s][1].y;
        o1.z = a1[s][1].z + dec * a2[s][1].z;
        o1.w = a1[s][1].w + dec * a2[s][1].w;
        ((float4*)(out + (size_t)node * DD))[colg * 2 + 0] = o0;
        ((float4*)(out + (size_t)node * DD))[colg * 2 + 1] = o1;
    }
}

// ---------------------------------------------------------------------------
// Edge kernel: warp per edge. lane = basis b (32 bases of 4x4 blocks).
// msg[b*4+o] = sum_i h[src][b*4+i] * W[type][b*16 + i*4 + o]
// scaled by edge_norm[e] * node_norm[dst[e]] (node_norm distributes over the
// segment sum), then red.global.add.v4.f32 directly into the output buffer
// (pre-filled with the dense part).
// ---------------------------------------------------------------------------
__global__ __launch_bounds__(256)
void edge_kernel(const float* __restrict__ h,
                 const int*   __restrict__ esrc,
                 const int*   __restrict__ edst,
                 const int*   __restrict__ etyp,
                 const float* __restrict__ enorm,
                 const float* __restrict__ nnorm,
                 const float* __restrict__ W,
                 float* __restrict__ out, int E)
{
    const int e = blockIdx.x * (blockDim.x >> 5) + (threadIdx.x >> 5);
    if (e >= E) return;
    const int lane = threadIdx.x & 31;

    const int s = __ldg(esrc + e);
    const int d = __ldg(edst + e);
    const int t = __ldg(etyp + e);
    const float sc = __ldg(enorm + e) * __ldg(nnorm + d);

    float4 hv = __ldg((const float4*)(h + (size_t)s * DD) + lane);

    const float4* wp = (const float4*)(W + (size_t)t * 512) + lane * 4;
    float4 w0 = __ldg(wp + 0);
    float4 w1 = __ldg(wp + 1);
    float4 w2 = __ldg(wp + 2);
    float4 w3 = __ldg(wp + 3);

    float4 m;
    m.x = hv.x * w0.x + hv.y * w1.x + hv.z * w2.x + hv.w * w3.x;
    m.y = hv.x * w0.y + hv.y * w1.y + hv.z * w2.y + hv.w * w3.y;
    m.z = hv.x * w0.z + hv.y * w1.z + hv.z * w2.z + hv.w * w3.z;
    m.w = hv.x * w0.w + hv.y * w1.w + hv.z * w2.w + hv.w * w3.w;
    m.x *= sc; m.y *= sc; m.z *= sc; m.w *= sc;

    float* dst = out + (size_t)d * DD + lane * 4;
    asm volatile("red.global.add.v4.f32 [%0], {%1,%2,%3,%4};"
                 :: "l"(dst), "f"(m.x), "f"(m.y), "f"(m.z), "f"(m.w)
                 : "memory");
}

__global__ void relu_kernel(float* __restrict__ x, int n)
{
    int i = blockIdx.x * blockDim.x + threadIdx.x;
    if (i < n) {
        float v = x[i];
        x[i] = v > 0.f ? v : 0.f;
    }
}

extern "C" void kernel_launch(void* const* d_in, const int* in_sizes, int n_in,
                              void* d_out, int out_size)
{
    const float* h   = (const float*)d_in[0];
    const float* fp  = (const float*)d_in[1];
    const float* sp  = (const float*)d_in[2];
    const float* td  = (const float*)d_in[3];
    const int*   es  = (const int*)  d_in[4];
    const int*   ed  = (const int*)  d_in[5];
    const int*   et  = (const int*)  d_in[6];
    const float* en  = (const float*)d_in[7];
    const float* nn  = (const float*)d_in[8];
    const float* W1  = (const float*)d_in[9];
    const float* W2  = (const float*)d_in[10];
    const float* lw1 = (const float*)d_in[11];
    const float* lw2 = (const float*)d_in[12];
    const float* tw1 = (const float*)d_in[13];
    const float* tw2 = (const float*)d_in[14];

    const int N = in_sizes[3];        // time_diff is (N,1)
    const int E = in_sizes[4];        // edge_src is (E,)

    float* h1 = (float*)d_out;
    float* h2 = h1 + (size_t)N * DD;

    const int denseBlocks = (N + NODES_PER_TILE - 1) / NODES_PER_TILE;
    const int edgeBlocks  = (E + 7) / 8;   // 8 warps per 256-thread block

    // Layer 1: dense part directly into h1, then scatter-add edge messages.
    dense_kernel<<<denseBlocks, 256>>>(h, fp, td, lw1, tw1, h1, N);
    edge_kernel <<<edgeBlocks, 256>>>(h, es, ed, et, en, nn, W1, h1, E);

    // Layer 2: consumes completed h1.
    dense_kernel<<<denseBlocks, 256>>>(h1, sp, td, lw2, tw2, h2, N);
    edge_kernel <<<edgeBlocks, 256>>>(h1, es, ed, et, en, nn, W2, h2, E);
    relu_kernel <<<((size_t)N * DD + 255) / 256, 256>>>(h2, N * DD);
}

// round 2
// speedup vs baseline: 1.1454x; 1.1454x over previous
#include <cuda_runtime.h>

#define DD 128
#define NODES_PER_TILE 64
#define E_MAX 800000
#define R_MAX 512
#define SPLIT 4

// ---- scratch (device globals; no allocation allowed) ----
__device__ int   g_off[R_MAX + 1];     // per-type offsets (exclusive scan)
__device__ int   g_cursor[R_MAX];      // scatter cursors
__device__ int   g_ssrc[E_MAX];        // sorted src
__device__ int   g_sdst[E_MAX];        // sorted dst
__device__ float g_sscale[E_MAX];      // sorted edge_norm * node_norm[dst]

// ---------------------------------------------------------------------------
// Dense kernel: out[n,:] = h[n,:] @ loop_w + exp(-td[n]*0.1) * (prev[n,:] @ time_w)
// ---------------------------------------------------------------------------
__global__ __launch_bounds__(256, 2)
void dense_kernel(const float* __restrict__ h,
                  const float* __restrict__ prev,
                  const float* __restrict__ time_diff,
                  const float* __restrict__ loop_w,
                  const float* __restrict__ time_w,
                  float* __restrict__ out, int N)
{
    __shared__ float w1s[16][DD];
    __shared__ float w2s[16][DD];
    __shared__ float hs[16][NODES_PER_TILE];
    __shared__ float ps[16][NODES_PER_TILE];

    const int tid  = threadIdx.x;
    const int colg = tid & 15;
    const int nrow = tid >> 4;
    const int tile = blockIdx.x * NODES_PER_TILE;

    float4 a1[4][2];
    float4 a2[4][2];
#pragma unroll
    for (int s = 0; s < 4; s++)
#pragma unroll
        for (int j = 0; j < 2; j++) {
            a1[s][j] = make_float4(0.f, 0.f, 0.f, 0.f);
            a2[s][j] = make_float4(0.f, 0.f, 0.f, 0.f);
        }

    const int stage_n  = tid >> 2;
    const int stage_c4 = tid & 3;
    const int stage_node = tile + stage_n;
    const bool stage_ok = (stage_node < N);

#pragma unroll 1
    for (int kc = 0; kc < 8; kc++) {
        const int k0 = kc * 16;
        __syncthreads();
#pragma unroll
        for (int r = 0; r < 2; r++) {
            int idx = tid + r * 256;
            int kk  = idx >> 5;
            int c4  = idx & 31;
            float4 v1 = ((const float4*)(loop_w + (size_t)(k0 + kk) * DD))[c4];
            float4 v2 = ((const float4*)(time_w + (size_t)(k0 + kk) * DD))[c4];
            ((float4*)&w1s[kk][0])[c4] = v1;
            ((float4*)&w2s[kk][0])[c4] = v2;
        }
        {
            float4 vh = make_float4(0.f, 0.f, 0.f, 0.f);
            float4 vp = make_float4(0.f, 0.f, 0.f, 0.f);
            if (stage_ok) {
                vh = ((const float4*)(h    + (size_t)stage_node * DD + k0))[stage_c4];
                vp = ((const float4*)(prev + (size_t)stage_node * DD + k0))[stage_c4];
            }
            int kk = stage_c4 * 4;
            hs[kk + 0][stage_n] = vh.x; hs[kk + 1][stage_n] = vh.y;
            hs[kk + 2][stage_n] = vh.z; hs[kk + 3][stage_n] = vh.w;
            ps[kk + 0][stage_n] = vp.x; ps[kk + 1][stage_n] = vp.y;
            ps[kk + 2][stage_n] = vp.z; ps[kk + 3][stage_n] = vp.w;
        }
        __syncthreads();

#pragma unroll
        for (int kk = 0; kk < 16; kk++) {
            float4 wa = ((const float4*)&w1s[kk][0])[colg * 2 + 0];
            float4 wb = ((const float4*)&w1s[kk][0])[colg * 2 + 1];
            float4 ua = ((const float4*)&w2s[kk][0])[colg * 2 + 0];
            float4 ub = ((const float4*)&w2s[kk][0])[colg * 2 + 1];
#pragma unroll
            for (int s = 0; s < 4; s++) {
                float hv = hs[kk][nrow + s * 16];
                float pv = ps[kk][nrow + s * 16];
                a1[s][0].x += hv * wa.x; a1[s][0].y += hv * wa.y;
                a1[s][0].z += hv * wa.z; a1[s][0].w += hv * wa.w;
                a1[s][1].x += hv * wb.x; a1[s][1].y += hv * wb.y;
                a1[s][1].z += hv * wb.z; a1[s][1].w += hv * wb.w;
                a2[s][0].x += pv * ua.x; a2[s][0].y += pv * ua.y;
                a2[s][0].z += pv * ua.z; a2[s][0].w += pv * ua.w;
                a2[s][1].x += pv * ub.x; a2[s][1].y += pv * ub.y;
                a2[s][1].z += pv * ub.z; a2[s][1].w += pv * ub.w;
            }
        }
    }

#pragma unroll
    for (int s = 0; s < 4; s++) {
        int node = tile + nrow + s * 16;
        if (node >= N) continue;
        float dec = __expf(-__ldg(time_diff + node) * 0.1f);
        float4 o0, o1;
        o0.x = a1[s][0].x + dec * a2[s][0].x;
        o0.y = a1[s][0].y + dec * a2[s][0].y;
        o0.z = a1[s][0].z + dec * a2[s][0].z;
        o0.w = a1[s][0].w + dec * a2[s][0].w;
        o1.x = a1[s][1].x + dec * a2[s][1].x;
        o1.y = a1[s][1].y + dec * a2[s][1].y;
        o1.z = a1[s][1].z + dec * a2[s][1].z;
        o1.w = a1[s][1].w + dec * a2[s][1].w;
        ((float4*)(out + (size_t)node * DD))[colg * 2 + 0] = o0;
        ((float4*)(out + (size_t)node * DD))[colg * 2 + 1] = o1;
    }
}

// ---------------------------------------------------------------------------
// Sort pipeline: counting sort of edges by relation type (R bins).
// ---------------------------------------------------------------------------
__global__ void zero_kernel(int R)
{
    int i = blockIdx.x * blockDim.x + threadIdx.x;
    if (i <= R) g_off[i] = 0;
    if (i < R)  g_cursor[i] = 0;
}

__global__ __launch_bounds__(256)
void hist_kernel(const int* __restrict__ etyp, int E, int R)
{
    __shared__ int lh[R_MAX];
    for (int i = threadIdx.x; i < R; i += blockDim.x) lh[i] = 0;
    __syncthreads();
    for (int e = blockIdx.x * blockDim.x + threadIdx.x; e < E;
         e += gridDim.x * blockDim.x)
        atomicAdd(&lh[__ldg(etyp + e)], 1);
    __syncthreads();
    for (int i = threadIdx.x; i < R; i += blockDim.x) {
        int v = lh[i];
        if (v) atomicAdd(&g_off[i + 1], v);
    }
}

__global__ void scan_kernel(int R)
{
    if (threadIdx.x == 0) {
        int acc = 0;
        for (int i = 1; i <= R; i++) { acc += g_off[i]; g_off[i] = acc; }
    }
}

__global__ __launch_bounds__(256)
void scatter_kernel(const int* __restrict__ esrc,
                    const int* __restrict__ edst,
                    const int* __restrict__ etyp,
                    const float* __restrict__ enorm,
                    const float* __restrict__ nnorm,
                    int E)
{
    for (int e = blockIdx.x * blockDim.x + threadIdx.x; e < E;
         e += gridDim.x * blockDim.x) {
        int t = __ldg(etyp + e);
        int d = __ldg(edst + e);
        int pos = g_off[t] + atomicAdd(&g_cursor[t], 1);
        g_ssrc[pos]   = __ldg(esrc + e);
        g_sdst[pos]   = d;
        g_sscale[pos] = __ldg(enorm + e) * __ldg(nnorm + d);
    }
}

// ---------------------------------------------------------------------------
// Sorted edge kernel: block = (type, chunk). W block for this type lives in
// registers for the whole loop (lane = basis index). Per edge: gather h[src]
// float4, 16 FMAs, red.global.add.v4 into out (pre-filled with dense part).
// ---------------------------------------------------------------------------
__global__ __launch_bounds__(256)
void edge_sorted_kernel(const float* __restrict__ h,
                        const float* __restrict__ W,
                        float* __restrict__ out)
{
    const int t    = blockIdx.x;
    const int lane = threadIdx.x & 31;
    const int warp = threadIdx.x >> 5;

    const int start = g_off[t];
    const int end   = g_off[t + 1];
    if (start >= end) return;

    // lane's 4x4 W block (row i of W maps h[...][b*4+i] to outputs)
    const float4* wp = (const float4*)(W + (size_t)t * 512) + lane * 4;
    const float4 w0 = __ldg(wp + 0);
    const float4 w1 = __ldg(wp + 1);
    const float4 w2 = __ldg(wp + 2);
    const float4 w3 = __ldg(wp + 3);

    for (int e = start + blockIdx.y * 8 + warp; e < end; e += 8 * SPLIT) {
        const int   s  = __ldg(g_ssrc + e);
        const int   d  = __ldg(g_sdst + e);
        const float sc = __ldg(g_sscale + e);

        float4 hv = __ldg((const float4*)(h + (size_t)s * DD) + lane);

        float4 m;
        m.x = hv.x * w0.x + hv.y * w1.x + hv.z * w2.x + hv.w * w3.x;
        m.y = hv.x * w0.y + hv.y * w1.y + hv.z * w2.y + hv.w * w3.y;
        m.z = hv.x * w0.z + hv.y * w1.z + hv.z * w2.z + hv.w * w3.z;
        m.w = hv.x * w0.w + hv.y * w1.w + hv.z * w2.w + hv.w * w3.w;
        m.x *= sc; m.y *= sc; m.z *= sc; m.w *= sc;

        float* dst = out + (size_t)d * DD + lane * 4;
        asm volatile("red.global.add.v4.f32 [%0], {%1,%2,%3,%4};"
                     :: "l"(dst), "f"(m.x), "f"(m.y), "f"(m.z), "f"(m.w)
                     : "memory");
    }
}

__global__ void relu_kernel(float* __restrict__ x, int n)
{
    int i = blockIdx.x * blockDim.x + threadIdx.x;
    if (i < n) {
        float v = x[i];
        x[i] = v > 0.f ? v : 0.f;
    }
}

extern "C" void kernel_launch(void* const* d_in, const int* in_sizes, int n_in,
                              void* d_out, int out_size)
{
    const float* h   = (const float*)d_in[0];
    const float* fp  = (const float*)d_in[1];
    const float* sp  = (const float*)d_in[2];
    const float* td  = (const float*)d_in[3];
    const int*   es  = (const int*)  d_in[4];
    const int*   ed  = (const int*)  d_in[5];
    const int*   et  = (const int*)  d_in[6];
    const float* en  = (const float*)d_in[7];
    const float* nn  = (const float*)d_in[8];
    const float* W1  = (const float*)d_in[9];
    const float* W2  = (const float*)d_in[10];
    const float* lw1 = (const float*)d_in[11];
    const float* lw2 = (const float*)d_in[12];
    const float* tw1 = (const float*)d_in[13];
    const float* tw2 = (const float*)d_in[14];

    const int N = in_sizes[3];            // time_diff is (N,1)
    const int E = in_sizes[4];            // edge_src is (E,)
    const int R = in_sizes[9] / 512;      // W1 is (R, 512)

    float* h1 = (float*)d_out;
    float* h2 = h1 + (size_t)N * DD;

    const int denseBlocks = (N + NODES_PER_TILE - 1) / NODES_PER_TILE;
    dim3 edgeGrid(R, SPLIT);

    // ---- sort edges by relation type (once, reused by both layers) ----
    zero_kernel   <<<(R + 256) / 256, 256>>>(R);
    hist_kernel   <<<256, 256>>>(et, E, R);
    scan_kernel   <<<1, 32>>>(R);
    scatter_kernel<<<512, 256>>>(es, ed, et, en, nn, E);

    // ---- layer 1 ----
    dense_kernel<<<denseBlocks, 256>>>(h, fp, td, lw1, tw1, h1, N);
    edge_sorted_kernel<<<edgeGrid, 256>>>(h, W1, h1);

    // ---- layer 2 ----
    dense_kernel<<<denseBlocks, 256>>>(h1, sp, td, lw2, tw2, h2, N);
    edge_sorted_kernel<<<edgeGrid, 256>>>(h1, W2, h2);
    relu_kernel<<<((size_t)N * DD + 255) / 256, 256>>>(h2, N * DD);
}

// round 3
// speedup vs baseline: 1.4011x; 1.2232x over previous
#include <cuda_runtime.h>

#define DD 128
#define NODES_PER_TILE 64
#define E_MAX 800000
#define R_MAX 512
#define SPLIT 8
#define SCHUNK 4096

// ---- scratch (device globals; no allocation allowed) ----
__device__ int   g_off[R_MAX + 1];     // per-type offsets (exclusive scan)
__device__ int   g_cursor[R_MAX];      // per-type reservation cursors
__device__ int   g_ssrc[E_MAX];        // sorted src
__device__ int   g_sdst[E_MAX];        // sorted dst
__device__ float g_sscale[E_MAX];      // sorted edge_norm * node_norm[dst]

// ---------------------------------------------------------------------------
// Dense kernel: out[n,:] = h[n,:] @ loop_w + exp(-td[n]*0.1) * (prev[n,:] @ time_w)
// ---------------------------------------------------------------------------
__global__ __launch_bounds__(256, 2)
void dense_kernel(const float* __restrict__ h,
                  const float* __restrict__ prev,
                  const float* __restrict__ time_diff,
                  const float* __restrict__ loop_w,
                  const float* __restrict__ time_w,
                  float* __restrict__ out, int N)
{
    __shared__ float w1s[16][DD];
    __shared__ float w2s[16][DD];
    __shared__ float hs[16][NODES_PER_TILE];
    __shared__ float ps[16][NODES_PER_TILE];

    const int tid  = threadIdx.x;
    const int colg = tid & 15;
    const int nrow = tid >> 4;
    const int tile = blockIdx.x * NODES_PER_TILE;

    float4 a1[4][2];
    float4 a2[4][2];
#pragma unroll
    for (int s = 0; s < 4; s++)
#pragma unroll
        for (int j = 0; j < 2; j++) {
            a1[s][j] = make_float4(0.f, 0.f, 0.f, 0.f);
            a2[s][j] = make_float4(0.f, 0.f, 0.f, 0.f);
        }

    const int stage_n  = tid >> 2;
    const int stage_c4 = tid & 3;
    const int stage_node = tile + stage_n;
    const bool stage_ok = (stage_node < N);

#pragma unroll 1
    for (int kc = 0; kc < 8; kc++) {
        const int k0 = kc * 16;
        __syncthreads();
#pragma unroll
        for (int r = 0; r < 2; r++) {
            int idx = tid + r * 256;
            int kk  = idx >> 5;
            int c4  = idx & 31;
            float4 v1 = ((const float4*)(loop_w + (size_t)(k0 + kk) * DD))[c4];
            float4 v2 = ((const float4*)(time_w + (size_t)(k0 + kk) * DD))[c4];
            ((float4*)&w1s[kk][0])[c4] = v1;
            ((float4*)&w2s[kk][0])[c4] = v2;
        }
        {
            float4 vh = make_float4(0.f, 0.f, 0.f, 0.f);
            float4 vp = make_float4(0.f, 0.f, 0.f, 0.f);
            if (stage_ok) {
                vh = ((const float4*)(h    + (size_t)stage_node * DD + k0))[stage_c4];
                vp = ((const float4*)(prev + (size_t)stage_node * DD + k0))[stage_c4];
            }
            int kk = stage_c4 * 4;
            hs[kk + 0][stage_n] = vh.x; hs[kk + 1][stage_n] = vh.y;
            hs[kk + 2][stage_n] = vh.z; hs[kk + 3][stage_n] = vh.w;
            ps[kk + 0][stage_n] = vp.x; ps[kk + 1][stage_n] = vp.y;
            ps[kk + 2][stage_n] = vp.z; ps[kk + 3][stage_n] = vp.w;
        }
        __syncthreads();

#pragma unroll
        for (int kk = 0; kk < 16; kk++) {
            float4 wa = ((const float4*)&w1s[kk][0])[colg * 2 + 0];
            float4 wb = ((const float4*)&w1s[kk][0])[colg * 2 + 1];
            float4 ua = ((const float4*)&w2s[kk][0])[colg * 2 + 0];
            float4 ub = ((const float4*)&w2s[kk][0])[colg * 2 + 1];
#pragma unroll
            for (int s = 0; s < 4; s++) {
                float hv = hs[kk][nrow + s * 16];
                float pv = ps[kk][nrow + s * 16];
                a1[s][0].x += hv * wa.x; a1[s][0].y += hv * wa.y;
                a1[s][0].z += hv * wa.z; a1[s][0].w += hv * wa.w;
                a1[s][1].x += hv * wb.x; a1[s][1].y += hv * wb.y;
                a1[s][1].z += hv * wb.z; a1[s][1].w += hv * wb.w;
                a2[s][0].x += pv * ua.x; a2[s][0].y += pv * ua.y;
                a2[s][0].z += pv * ua.z; a2[s][0].w += pv * ua.w;
                a2[s][1].x += pv * ub.x; a2[s][1].y += pv * ub.y;
                a2[s][1].z += pv * ub.z; a2[s][1].w += pv * ub.w;
            }
        }
    }

#pragma unroll
    for (int s = 0; s < 4; s++) {
        int node = tile + nrow + s * 16;
        if (node >= N) continue;
        float dec = __expf(-__ldg(time_diff + node) * 0.1f);
        float4 o0, o1;
        o0.x = a1[s][0].x + dec * a2[s][0].x;
        o0.y = a1[s][0].y + dec * a2[s][0].y;
        o0.z = a1[s][0].z + dec * a2[s][0].z;
        o0.w = a1[s][0].w + dec * a2[s][0].w;
        o1.x = a1[s][1].x + dec * a2[s][1].x;
        o1.y = a1[s][1].y + dec * a2[s][1].y;
        o1.z = a1[s][1].z + dec * a2[s][1].z;
        o1.w = a1[s][1].w + dec * a2[s][1].w;
        ((float4*)(out + (size_t)node * DD))[colg * 2 + 0] = o0;
        ((float4*)(out + (size_t)node * DD))[colg * 2 + 1] = o1;
    }
}

// ---------------------------------------------------------------------------
// Sort pipeline: counting sort of edges by relation type (R bins).
// ---------------------------------------------------------------------------
__global__ void zero_kernel(int R)
{
    int i = blockIdx.x * blockDim.x + threadIdx.x;
    if (i <= R) g_off[i] = 0;
    if (i < R)  g_cursor[i] = 0;
}

__global__ __launch_bounds__(256)
void hist_kernel(const int* __restrict__ etyp, int E, int R)
{
    __shared__ int lh[R_MAX];
    for (int i = threadIdx.x; i < R; i += blockDim.x) lh[i] = 0;
    __syncthreads();
    for (int e = blockIdx.x * blockDim.x + threadIdx.x; e < E;
         e += gridDim.x * blockDim.x)
        atomicAdd(&lh[__ldg(etyp + e)], 1);
    __syncthreads();
    for (int i = threadIdx.x; i < R; i += blockDim.x) {
        int v = lh[i];
        if (v) atomicAdd(&g_off[i + 1], v);
    }
}

__global__ void scan_kernel(int R)
{
    if (threadIdx.x == 0) {
        int acc = 0;
        for (int i = 1; i <= R; i++) { acc += g_off[i]; g_off[i] = acc; }
    }
}

// Two-level scatter: block = one SCHUNK of edges.
// Pass A: smem histogram. Pass B: one global atomicAdd per (block,type) to
// reserve a range. Pass C: rank within block via smem cursors, write out.
__global__ __launch_bounds__(256)
void scatter_kernel(const int* __restrict__ esrc,
                    const int* __restrict__ edst,
                    const int* __restrict__ etyp,
                    const float* __restrict__ enorm,
                    const float* __restrict__ nnorm,
                    int E, int R)
{
    __shared__ int lbase[R_MAX];
    __shared__ int lcur[R_MAX];

    const int e0 = blockIdx.x * SCHUNK;
    const int e1 = min(e0 + SCHUNK, E);

    for (int i = threadIdx.x; i < R; i += blockDim.x) {
        lbase[i] = 0;
        lcur[i]  = 0;
    }
    __syncthreads();

    // Pass A: local histogram
    for (int e = e0 + threadIdx.x; e < e1; e += blockDim.x)
        atomicAdd(&lbase[__ldg(etyp + e)], 1);
    __syncthreads();

    // Pass B: reserve global ranges (one atomic per non-empty type)
    for (int i = threadIdx.x; i < R; i += blockDim.x) {
        int cnt = lbase[i];
        lbase[i] = cnt ? (g_off[i] + atomicAdd(&g_cursor[i], cnt)) : 0;
    }
    __syncthreads();

    // Pass C: rank + write
    for (int e = e0 + threadIdx.x; e < e1; e += blockDim.x) {
        int t = __ldg(etyp + e);
        int d = __ldg(edst + e);
        int pos = lbase[t] + atomicAdd(&lcur[t], 1);
        g_ssrc[pos]   = __ldg(esrc + e);
        g_sdst[pos]   = d;
        g_sscale[pos] = __ldg(enorm + e) * __ldg(nnorm + d);
    }
}

// ---------------------------------------------------------------------------
// Sorted edge kernel: block = (type, chunk). W block for this type lives in
// registers (lane = basis index). Per edge: gather h[src] float4, 16 FMAs,
// red.global.add.v4 into out (pre-filled with dense part).
// ---------------------------------------------------------------------------
__global__ __launch_bounds__(256)
void edge_sorted_kernel(const float* __restrict__ h,
                        const float* __restrict__ W,
                        float* __restrict__ out)
{
    const int t    = blockIdx.x;
    const int lane = threadIdx.x & 31;
    const int warp = threadIdx.x >> 5;

    const int start = g_off[t];
    const int end   = g_off[t + 1];
    if (start >= end) return;

    const float4* wp = (const float4*)(W + (size_t)t * 512) + lane * 4;
    const float4 w0 = __ldg(wp + 0);
    const float4 w1 = __ldg(wp + 1);
    const float4 w2 = __ldg(wp + 2);
    const float4 w3 = __ldg(wp + 3);

    for (int e = start + blockIdx.y * 8 + warp; e < end; e += 8 * SPLIT) {
        const int   s  = __ldg(g_ssrc + e);
        const int   d  = __ldg(g_sdst + e);
        const float sc = __ldg(g_sscale + e);

        float4 hv = __ldg((const float4*)(h + (size_t)s * DD) + lane);

        float4 m;
        m.x = hv.x * w0.x + hv.y * w1.x + hv.z * w2.x + hv.w * w3.x;
        m.y = hv.x * w0.y + hv.y * w1.y + hv.z * w2.y + hv.w * w3.y;
        m.z = hv.x * w0.z + hv.y * w1.z + hv.z * w2.z + hv.w * w3.z;
        m.w = hv.x * w0.w + hv.y * w1.w + hv.z * w2.w + hv.w * w3.w;
        m.x *= sc; m.y *= sc; m.z *= sc; m.w *= sc;

        float* dst = out + (size_t)d * DD + lane * 4;
        asm volatile("red.global.add.v4.f32 [%0], {%1,%2,%3,%4};"
                     :: "l"(dst), "f"(m.x), "f"(m.y), "f"(m.z), "f"(m.w)
                     : "memory");
    }
}

__global__ void relu_kernel(float* __restrict__ x, int n)
{
    int i = blockIdx.x * blockDim.x + threadIdx.x;
    if (i < n) {
        float v = x[i];
        x[i] = v > 0.f ? v : 0.f;
    }
}

extern "C" void kernel_launch(void* const* d_in, const int* in_sizes, int n_in,
                              void* d_out, int out_size)
{
    const float* h   = (const float*)d_in[0];
    const float* fp  = (const float*)d_in[1];
    const float* sp  = (const float*)d_in[2];
    const float* td  = (const float*)d_in[3];
    const int*   es  = (const int*)  d_in[4];
    const int*   ed  = (const int*)  d_in[5];
    const int*   et  = (const int*)  d_in[6];
    const float* en  = (const float*)d_in[7];
    const float* nn  = (const float*)d_in[8];
    const float* W1  = (const float*)d_in[9];
    const float* W2  = (const float*)d_in[10];
    const float* lw1 = (const float*)d_in[11];
    const float* lw2 = (const float*)d_in[12];
    const float* tw1 = (const float*)d_in[13];
    const float* tw2 = (const float*)d_in[14];

    const int N = in_sizes[3];            // time_diff is (N,1)
    const int E = in_sizes[4];            // edge_src is (E,)
    const int R = in_sizes[9] / 512;      // W1 is (R, 512)

    float* h1 = (float*)d_out;
    float* h2 = h1 + (size_t)N * DD;

    const int denseBlocks   = (N + NODES_PER_TILE - 1) / NODES_PER_TILE;
    const int scatterBlocks = (E + SCHUNK - 1) / SCHUNK;
    dim3 edgeGrid(R, SPLIT);

    // ---- sort edges by relation type (once, reused by both layers) ----
    zero_kernel   <<<(R + 256) / 256, 256>>>(R);
    hist_kernel   <<<256, 256>>>(et, E, R);
    scan_kernel   <<<1, 32>>>(R);
    scatter_kernel<<<scatterBlocks, 256>>>(es, ed, et, en, nn, E, R);

    // ---- layer 1 ----
    dense_kernel<<<denseBlocks, 256>>>(h, fp, td, lw1, tw1, h1, N);
    edge_sorted_kernel<<<edgeGrid, 256>>>(h, W1, h1);

    // ---- layer 2 ----
    dense_kernel<<<denseBlocks, 256>>>(h1, sp, td, lw2, tw2, h2, N);
    edge_sorted_kernel<<<edgeGrid, 256>>>(h1, W2, h2);
    relu_kernel<<<((size_t)N * DD + 255) / 256, 256>>>(h2, N * DD);
}